// round 5
// baseline (speedup 1.0000x reference)
#include <cuda_runtime.h>
#include <cuda_fp16.h>
#include <cstdint>
#include <math.h>

// ---------------- problem constants ----------------
constexpr int NB   = 1024;
constexpr int NH   = 1024;
constexpr int NI   = 69;
constexpr int NSRC = 50;
constexpr int NDEC = 24;
constexpr int NT   = 74;
constexpr int KX   = 128;
constexpr int KA   = NH + KX;     // 1152
constexpr int NCHUNK = KA / 64;   // 18

constexpr int STAGE = 65536;              // A 16KB + B 6x8KB
constexpr int SPILL_OFF = 2 * STAGE;      // 131072: h_n spill 128x64 fp32
constexpr int SMEM_BYTES = SPILL_OFF + 128 * 64 * 4;   // 163840

// ---------------- device scratch ----------------
__device__ __align__(16) float  g_h32[2][NB * NH];
__device__ __align__(16) __half g_ah[2][NB * KA];      // fp16 aug activations [b][k] = h|x
__device__ __align__(16) __half g_wBhi[4 * KA * NH];   // [g][k][j]
__device__ __align__(16) __half g_wBlo[4 * KA * NH];
__device__ __align__(16) float  g_x32[NB * KX];
__device__ __align__(16) float  g_outb[NT * NB * NI];
__device__ __align__(16) float  g_part[8 * NB * NI];

// ---------------- asm helpers (base PTX only) ----------------
__device__ __forceinline__ uint32_t smem_u32(const void* p) {
    uint32_t a;
    asm("{ .reg .u64 t; cvta.to.shared.u64 t, %1; cvt.u32.u64 %0, t; }" : "=r"(a) : "l"(p));
    return a;
}
__device__ __forceinline__ void cp16(uint32_t dst, const void* src) {
    asm volatile("cp.async.cg.shared.global [%0], [%1], 16;" :: "r"(dst), "l"(src));
}
__device__ __forceinline__ void cp_commit() {
    asm volatile("cp.async.commit_group;" ::: "memory");
}
__device__ __forceinline__ void ldsm4(uint32_t* r, uint32_t addr) {
    asm volatile("ldmatrix.sync.aligned.m8n8.x4.shared.b16 {%0,%1,%2,%3}, [%4];"
        : "=r"(r[0]), "=r"(r[1]), "=r"(r[2]), "=r"(r[3]) : "r"(addr));
}
__device__ __forceinline__ void ldsm4t(uint32_t* r, uint32_t addr) {
    asm volatile("ldmatrix.sync.aligned.m8n8.x4.trans.shared.b16 {%0,%1,%2,%3}, [%4];"
        : "=r"(r[0]), "=r"(r[1]), "=r"(r[2]), "=r"(r[3]) : "r"(addr));
}
__device__ __forceinline__ void mma16816(float* d, const uint32_t* a, const uint32_t* b) {
    asm volatile("mma.sync.aligned.m16n8k16.row.col.f32.f16.f16.f32 "
        "{%0,%1,%2,%3}, {%4,%5,%6,%7}, {%8,%9}, {%0,%1,%2,%3};"
        : "+f"(d[0]), "+f"(d[1]), "+f"(d[2]), "+f"(d[3])
        : "r"(a[0]), "r"(a[1]), "r"(a[2]), "r"(a[3]), "r"(b[0]), "r"(b[1]));
}

// ---------------- prep: per-gate K-major split-fp16 weights ----------------
__global__ void k_prep(const float* __restrict__ w_ih, const float* __restrict__ w_hh) {
    size_t idx = (size_t)blockIdx.x * blockDim.x + threadIdx.x;
    if (idx >= (size_t)4 * KA * NH) return;
    int j = (int)(idx % NH);
    int t = (int)(idx / NH);
    int k = t % KA;
    int g = t / KA;
    float v = 0.0f;
    if (g == 0) {
        if (k < NH) v = w_hh[(size_t)j * NH + k];
        else if (k - NH < NI) v = w_ih[(size_t)j * NI + (k - NH)];
    } else if (g == 1) {
        if (k < NH) v = w_hh[(size_t)(NH + j) * NH + k];
        else if (k - NH < NI) v = w_ih[(size_t)(NH + j) * NI + (k - NH)];
    } else if (g == 2) {
        if (k >= NH && k - NH < NI) v = w_ih[(size_t)(2 * NH + j) * NI + (k - NH)];
    } else {
        if (k < NH) v = w_hh[(size_t)(2 * NH + j) * NH + k];
    }
    __half hi = __float2half(v);
    g_wBhi[idx] = hi;
    g_wBlo[idx] = __float2half(v - __half2float(hi));
}

__global__ void k_init() {
    int idx = blockIdx.x * blockDim.x + threadIdx.x;
    if (idx < NB * KA) {
        g_ah[0][idx] = __float2half(0.0f);
        g_ah[1][idx] = __float2half(0.0f);
    }
    if (idx < NB * NH) g_h32[0][idx] = 0.0f;
}

__global__ void k_setx(const float* __restrict__ src, int stride, int buf) {
    int idx = blockIdx.x * blockDim.x + threadIdx.x;
    if (idx >= NB * KX) return;
    int b = idx >> 7, c = idx & (KX - 1);
    float v = (c < NI) ? src[(size_t)b * stride + c] : 0.0f;
    g_x32[idx] = v;
    g_ah[buf][(size_t)b * KA + NH + c] = __float2half(v);
}

// ---------------- fused GRU step ----------------
// grid (16 j-tiles, 8 m-tiles), 768 threads = 24 warps.
// warp w: gate = w>>3 (0=r, 1=z, 2=n-slot), mq = w&7 (16-row slice).
// n-slot accumulates h_n over chunks 0..15, spills to smem, then i_n over 16..17.
__global__ void __launch_bounds__(768, 1)
k_gru(int cur, const float* __restrict__ bih, const float* __restrict__ bhh) {
    extern __shared__ char sm[];
    const uint32_t sb = smem_u32(sm);
    const int tid = threadIdx.x;
    const int wid = tid >> 5, l = tid & 31;
    const int gate = wid >> 3, mq = wid & 7;
    const int m0 = blockIdx.y * 128;
    const int j0 = blockIdx.x * 64;
    const int nxt = cur ^ 1;

    const __half* A = g_ah[cur];

    float d[8][4] = {};

    auto load_chunk = [&](int c) {
        const uint32_t st = sb + (c & 1) * STAGE;
        // 4096 granules: A 1024 (128m x 8kg) then B 3072 (6 tiles x 64k x 8cg)
        #pragma unroll
        for (int i = 0; i < 6; i++) {
            int v = tid + i * 768;
            if (v < 1024) {
                int m = v >> 3, kg = v & 7;
                cp16(st + m * 128 + ((kg ^ (m & 7)) << 4),
                     A + (size_t)(m0 + m) * KA + c * 64 + kg * 8);
            } else if (v < 4096) {
                int u = v - 1024;
                int tb = u >> 9;               // 0..5 = slot*2 + pass
                int s = tb >> 1, p = tb & 1;
                int r = (u >> 3) & 63, cg = u & 7;
                int g = (s < 2) ? s : ((c < 16) ? 3 : 2);
                const __half* W = p ? g_wBlo : g_wBhi;
                cp16(st + 16384 + tb * 8192 + r * 128 + ((cg ^ (r & 7)) << 4),
                     W + ((size_t)g * KA + c * 64 + r) * NH + j0 + cg * 8);
            }
        }
        cp_commit();
    };

    float* spill = (float*)(sm + SPILL_OFF);   // [128][64]

    load_chunk(0);
    for (int c = 0; c < NCHUNK; c++) {
        if (c + 1 < NCHUNK) {
            load_chunk(c + 1);
            asm volatile("cp.async.wait_group 1;" ::: "memory");
        } else {
            asm volatile("cp.async.wait_group 0;" ::: "memory");
        }
        __syncthreads();

        // n-slot boundary: stash h_n accum, restart for i_n
        if (c == 16 && gate == 2) {
            int r0 = mq * 16 + (l >> 2);
            int cc = (l & 3) * 2;
            #pragma unroll
            for (int nb = 0; nb < 8; nb++) {
                *(float2*)&spill[r0 * 64 + nb * 8 + cc]       = make_float2(d[nb][0], d[nb][1]);
                *(float2*)&spill[(r0 + 8) * 64 + nb * 8 + cc] = make_float2(d[nb][2], d[nb][3]);
                d[nb][0] = d[nb][1] = d[nb][2] = d[nb][3] = 0.0f;
            }
        }

        const uint32_t st = sb + (c & 1) * STAGE;
        #pragma unroll
        for (int kk = 0; kk < 4; kk++) {
            uint32_t a[4];
            {
                int m = mq * 16 + (l & 15);
                int kg = kk * 2 + (l >> 4);
                ldsm4(a, st + m * 128 + ((kg ^ (m & 7)) << 4));
            }
            #pragma unroll
            for (int p = 0; p < 2; p++) {
                const uint32_t bbase = st + 16384 + (gate * 2 + p) * 8192;
                uint32_t b[4][4];
                #pragma unroll
                for (int nq = 0; nq < 4; nq++) {
                    int k = kk * 16 + (l & 15);
                    int ng = nq * 2 + (l >> 4);
                    ldsm4t(b[nq], bbase + k * 128 + ((ng ^ (k & 7)) << 4));
                }
                #pragma unroll
                for (int nb = 0; nb < 8; nb++)
                    mma16816(d[nb], a, b[nb >> 1] + (nb & 1) * 2);
            }
        }
        __syncthreads();
    }

    // ---- epilogue: planes r | z | i_n in sC; h_n in spill ----
    float* sC = (float*)sm;   // [128][196]
    {
        int r0 = mq * 16 + (l >> 2);
        int cc = gate * 64 + (l & 3) * 2;
        #pragma unroll
        for (int nb = 0; nb < 8; nb++) {
            *(float2*)&sC[r0 * 196 + cc + nb * 8]       = make_float2(d[nb][0], d[nb][1]);
            *(float2*)&sC[(r0 + 8) * 196 + cc + nb * 8] = make_float2(d[nb][2], d[nb][3]);
        }
    }
    __syncthreads();

    #pragma unroll
    for (int i = 0; i < 11; i++) {
        int idx = i * 768 + tid;
        if (idx >= 128 * 64) break;
        int m = idx >> 6, j = idx & 63;
        int jg = j0 + j;
        float rc = sC[m * 196 + j];
        float zc = sC[m * 196 + 64 + j];
        float ic = sC[m * 196 + 128 + j];
        float hc = spill[m * 64 + j];
        float br  = __ldg(&bih[jg]) + __ldg(&bhh[jg]);
        float bz  = __ldg(&bih[NH + jg]) + __ldg(&bhh[NH + jg]);
        float bin = __ldg(&bih[2 * NH + jg]);
        float bhn = __ldg(&bhh[2 * NH + jg]);
        float r = 1.0f / (1.0f + expf(-(rc + br)));
        float z = 1.0f / (1.0f + expf(-(zc + bz)));
        float n = tanhf(ic + bin + r * (hc + bhn));
        float hold = g_h32[cur][(size_t)(m0 + m) * NH + jg];
        float hnew = (1.0f - z) * n + z * hold;
        g_h32[nxt][(size_t)(m0 + m) * NH + jg] = hnew;
        g_ah[nxt][(size_t)(m0 + m) * KA + jg] = __float2half(hnew);
    }
}

// ---------------- decode fc1: split-K partials (fp32 SIMT) ----------------
__global__ void k_out(const float* __restrict__ fc1w, int p) {
    __shared__ float As[32][68];
    __shared__ float Bs[32][80];
    const float* hh = g_h32[p];
    const int m0 = blockIdx.x * 64;
    const int ks = blockIdx.y;
    const int tid = threadIdx.x;
    const int tx = tid & 15, ty = tid >> 4;
    float acc[4][5] = {};
    for (int kt = 0; kt < 4; kt++) {
        int k0 = ks * 128 + kt * 32;
        #pragma unroll
        for (int u = 0; u < 2; u++) {
            int idx = tid + u * 256;
            int m = idx >> 3;
            int kq = (idx & 7) * 4;
            float4 va = *(const float4*)(hh + (size_t)(m0 + m) * NH + k0 + kq);
            As[kq + 0][m] = va.x; As[kq + 1][m] = va.y;
            As[kq + 2][m] = va.z; As[kq + 3][m] = va.w;
        }
        for (int idx = tid; idx < 80 * 32; idx += 256) {
            int n = idx >> 5, k = idx & 31;
            Bs[k][n] = (n < NI) ? fc1w[(size_t)n * NH + k0 + k] : 0.0f;
        }
        __syncthreads();
        #pragma unroll
        for (int k = 0; k < 32; k++) {
            float4 a4 = *(const float4*)&As[k][ty * 4];
            float a[4] = {a4.x, a4.y, a4.z, a4.w};
            float bb[5];
            #pragma unroll
            for (int j = 0; j < 5; j++) bb[j] = Bs[k][tx * 5 + j];
            #pragma unroll
            for (int i = 0; i < 4; i++)
                #pragma unroll
                for (int j = 0; j < 5; j++)
                    acc[i][j] += a[i] * bb[j];
        }
        __syncthreads();
    }
    #pragma unroll
    for (int i = 0; i < 4; i++) {
        int m = m0 + ty * 4 + i;
        #pragma unroll
        for (int j = 0; j < 5; j++) {
            int n = tx * 5 + j;
            if (n < NI)
                g_part[(size_t)ks * NB * NI + (size_t)m * NI + n] = acc[i][j];
        }
    }
}

__global__ void k_outred(const float* __restrict__ fc1b, int t, int nbuf) {
    int idx = blockIdx.x * blockDim.x + threadIdx.x;
    if (idx >= NB * NI) return;
    int b = idx / NI, i = idx - b * NI;
    float s = g_x32[(size_t)b * KX + i] + fc1b[i];
    #pragma unroll
    for (int p = 0; p < 8; p++) s += g_part[(size_t)p * NB * NI + idx];
    g_outb[(size_t)t * NB * NI + idx] = s;
    g_x32[(size_t)b * KX + i] = s;
    g_ah[nbuf][(size_t)b * KA + NH + i] = __float2half(s);
}

__global__ void k_final(const float* __restrict__ fc2w, const float* __restrict__ fc2b,
                        float* __restrict__ y) {
    int b = blockIdx.x;
    float s = 0.0f;
    for (int f = threadIdx.x; f < NT * NI; f += 256) {
        int t = f / NI, i = f - t * NI;
        s += g_outb[(size_t)t * NB * NI + (size_t)b * NI + i] * fc2w[f];
    }
    __shared__ float red[256];
    red[threadIdx.x] = s;
    __syncthreads();
    for (int off = 128; off > 0; off >>= 1) {
        if (threadIdx.x < off) red[threadIdx.x] += red[threadIdx.x + off];
        __syncthreads();
    }
    if (threadIdx.x == 0)
        y[b] = 1.0f / (1.0f + expf(-(red[0] + fc2b[0])));
}

// ---------------- launch ----------------
extern "C" void kernel_launch(void* const* d_in, const int* in_sizes, int n_in,
                              void* d_out, int out_size) {
    const float* enc  = (const float*)d_in[0];
    const float* dec  = (const float*)d_in[1];
    const float* w_ih = (const float*)d_in[2];
    const float* w_hh = (const float*)d_in[3];
    const float* b_ih = (const float*)d_in[4];
    const float* b_hh = (const float*)d_in[5];
    const float* fc1w = (const float*)d_in[6];
    const float* fc1b = (const float*)d_in[7];
    const float* fc2w = (const float*)d_in[8];
    const float* fc2b = (const float*)d_in[9];
    float* y = (float*)d_out;

    cudaFuncSetAttribute(k_gru, cudaFuncAttributeMaxDynamicSharedMemorySize, SMEM_BYTES);

    k_prep<<<(int)(((size_t)4 * KA * NH + 255) / 256), 256>>>(w_ih, w_hh);
    k_init<<<(NB * KA + 255) / 256, 256>>>();

    int cur = 0;
    for (int s = 0; s < 2 * NT; ++s) {
        if (s <= NT) {
            int f = (s == NT) ? 0 : s;
            const float* src;
            int stride;
            if (f < NSRC) { src = enc + (size_t)f * NI; stride = NSRC * NI; }
            else          { src = dec + (size_t)(f - NSRC) * NI; stride = NDEC * NI; }
            k_setx<<<(NB * KX + 255) / 256, 256>>>(src, stride, cur);
        }
        k_gru<<<dim3(16, 8), 768, SMEM_BYTES>>>(cur, b_ih, b_hh);
        if (s >= NT) {
            k_out<<<dim3(16, 8), 256>>>(fc1w, cur ^ 1);
            k_outred<<<(NB * NI + 255) / 256, 256>>>(fc1b, s - NT, cur ^ 1);
        }
        cur ^= 1;
    }
    k_final<<<NB, 256>>>(fc2w, fc2b, y);
}

// round 6
// speedup vs baseline: 1.4930x; 1.4930x over previous
#include <cuda_runtime.h>
#include <cuda_fp16.h>
#include <cstdint>
#include <math.h>

// ---------------- problem constants ----------------
constexpr int NB   = 1024;
constexpr int NH   = 1024;
constexpr int NI   = 69;
constexpr int NSRC = 50;
constexpr int NDEC = 24;
constexpr int NT   = 74;
constexpr int KX   = 128;
constexpr int KA   = NH + KX;     // 1152
constexpr int NCHUNK = KA / 64;   // 18

constexpr int STG  = 40960;               // A 16KB + B 3x8KB
constexpr int SPILL_OFF = 100352;         // after epilogue sC (128x196 fp32)
constexpr int SMEM_BYTES = SPILL_OFF + 128 * 64 * 4;   // 133120

// ---------------- device scratch ----------------
__device__ __align__(16) float  g_h32[2][NB * NH];
__device__ __align__(16) __half g_ah[2][NB * KA];    // fp16 aug activations [b][k] = h|x
__device__ __align__(16) __half g_wB[4 * KA * NH];   // [g][k][j] single-pass fp16
__device__ __align__(16) float  g_x32[NB * KX];
__device__ __align__(16) float  g_outb[NT * NB * NI];
__device__ __align__(16) float  g_part[8 * NB * NI];

// ---------------- asm helpers (base PTX only) ----------------
__device__ __forceinline__ uint32_t smem_u32(const void* p) {
    uint32_t a;
    asm("{ .reg .u64 t; cvta.to.shared.u64 t, %1; cvt.u32.u64 %0, t; }" : "=r"(a) : "l"(p));
    return a;
}
__device__ __forceinline__ void cp16(uint32_t dst, const void* src) {
    asm volatile("cp.async.cg.shared.global [%0], [%1], 16;" :: "r"(dst), "l"(src));
}
__device__ __forceinline__ void cp_commit() {
    asm volatile("cp.async.commit_group;" ::: "memory");
}
__device__ __forceinline__ void ldsm4(uint32_t* r, uint32_t addr) {
    asm volatile("ldmatrix.sync.aligned.m8n8.x4.shared.b16 {%0,%1,%2,%3}, [%4];"
        : "=r"(r[0]), "=r"(r[1]), "=r"(r[2]), "=r"(r[3]) : "r"(addr));
}
__device__ __forceinline__ void ldsm4t(uint32_t* r, uint32_t addr) {
    asm volatile("ldmatrix.sync.aligned.m8n8.x4.trans.shared.b16 {%0,%1,%2,%3}, [%4];"
        : "=r"(r[0]), "=r"(r[1]), "=r"(r[2]), "=r"(r[3]) : "r"(addr));
}
__device__ __forceinline__ void mma16816(float* d, const uint32_t* a, const uint32_t* b) {
    asm volatile("mma.sync.aligned.m16n8k16.row.col.f32.f16.f16.f32 "
        "{%0,%1,%2,%3}, {%4,%5,%6,%7}, {%8,%9}, {%0,%1,%2,%3};"
        : "+f"(d[0]), "+f"(d[1]), "+f"(d[2]), "+f"(d[3])
        : "r"(a[0]), "r"(a[1]), "r"(a[2]), "r"(a[3]), "r"(b[0]), "r"(b[1]));
}

// ---------------- prep: per-gate K-major fp16 weights ----------------
// [g][k][j]: g0 r = [whh_r|wih_r], g1 z = [whh_z|wih_z],
//            g2 i_n = [0|wih_n],  g3 h_n = [whh_n|0]
__global__ void k_prep(const float* __restrict__ w_ih, const float* __restrict__ w_hh) {
    size_t idx = (size_t)blockIdx.x * blockDim.x + threadIdx.x;
    if (idx >= (size_t)4 * KA * NH) return;
    int j = (int)(idx % NH);
    int t = (int)(idx / NH);
    int k = t % KA;
    int g = t / KA;
    float v = 0.0f;
    if (g == 0) {
        if (k < NH) v = w_hh[(size_t)j * NH + k];
        else if (k - NH < NI) v = w_ih[(size_t)j * NI + (k - NH)];
    } else if (g == 1) {
        if (k < NH) v = w_hh[(size_t)(NH + j) * NH + k];
        else if (k - NH < NI) v = w_ih[(size_t)(NH + j) * NI + (k - NH)];
    } else if (g == 2) {
        if (k >= NH && k - NH < NI) v = w_ih[(size_t)(2 * NH + j) * NI + (k - NH)];
    } else {
        if (k < NH) v = w_hh[(size_t)(2 * NH + j) * NH + k];
    }
    g_wB[idx] = __float2half(v);
}

__global__ void k_init() {
    int idx = blockIdx.x * blockDim.x + threadIdx.x;
    if (idx < NB * KA) {
        g_ah[0][idx] = __float2half(0.0f);
        g_ah[1][idx] = __float2half(0.0f);
    }
    if (idx < NB * NH) g_h32[0][idx] = 0.0f;
}

__global__ void k_setx(const float* __restrict__ src, int stride, int buf) {
    int idx = blockIdx.x * blockDim.x + threadIdx.x;
    if (idx >= NB * KX) return;
    int b = idx >> 7, c = idx & (KX - 1);
    float v = (c < NI) ? src[(size_t)b * stride + c] : 0.0f;
    g_x32[idx] = v;
    g_ah[buf][(size_t)b * KA + NH + c] = __float2half(v);
}

// ---------------- fused GRU step ----------------
// grid (16 j-tiles, 8 m-tiles), 384 threads = 12 warps.
// warp: gate = wid>>2 (0=r,1=z,2=n-slot), mh = (wid>>1)&1, nhf = wid&1.
// warp tile 64m x 32n. n-slot: h_n over chunks 0..15 (spill), i_n over 16..17.
__global__ void __launch_bounds__(384, 1)
k_gru(int cur, const float* __restrict__ bih, const float* __restrict__ bhh) {
    extern __shared__ char sm[];
    const uint32_t sb = smem_u32(sm);
    const int tid = threadIdx.x;
    const int wid = tid >> 5, l = tid & 31;
    const int gate = wid >> 2;
    const int mh = (wid >> 1) & 1, nhf = wid & 1;
    const int m0 = blockIdx.y * 128;
    const int j0 = blockIdx.x * 64;
    const int nxt = cur ^ 1;

    const __half* A = g_ah[cur];

    float d[4][4][4] = {};   // [mt][nb][frag]

    auto load_chunk = [&](int c) {
        const uint32_t st = sb + (c & 1) * STG;
        // 2560 granules: A 1024 (128m x 8kg), B 1536 (3 slots x 64k x 8cg)
        #pragma unroll
        for (int i = 0; i < 7; i++) {
            int v = tid + i * 384;
            if (v < 1024) {
                int m = v >> 3, kg = v & 7;
                cp16(st + m * 128 + ((kg ^ (m & 7)) << 4),
                     A + (size_t)(m0 + m) * KA + c * 64 + kg * 8);
            } else if (v < 2560) {
                int u = v - 1024;
                int tb = u >> 9;                 // 0..2 gate slot
                int r = (u >> 3) & 63, cg = u & 7;
                int g = (tb < 2) ? tb : ((c < 16) ? 3 : 2);
                cp16(st + 16384 + tb * 8192 + r * 128 + ((cg ^ (r & 7)) << 4),
                     g_wB + ((size_t)g * KA + c * 64 + r) * NH + j0 + cg * 8);
            }
        }
        cp_commit();
    };

    float* spill = (float*)(sm + SPILL_OFF);   // [128][64]

    load_chunk(0);
    for (int c = 0; c < NCHUNK; c++) {
        if (c + 1 < NCHUNK) {
            load_chunk(c + 1);
            asm volatile("cp.async.wait_group 1;" ::: "memory");
        } else {
            asm volatile("cp.async.wait_group 0;" ::: "memory");
        }
        __syncthreads();

        // n-slot boundary: stash h_n accum, restart for i_n
        if (c == 16 && gate == 2) {
            #pragma unroll
            for (int mt = 0; mt < 4; mt++) {
                int r0 = mh * 64 + mt * 16 + (l >> 2);
                int cc = nhf * 32 + (l & 3) * 2;
                #pragma unroll
                for (int nb = 0; nb < 4; nb++) {
                    *(float2*)&spill[r0 * 64 + nb * 8 + cc] =
                        make_float2(d[mt][nb][0], d[mt][nb][1]);
                    *(float2*)&spill[(r0 + 8) * 64 + nb * 8 + cc] =
                        make_float2(d[mt][nb][2], d[mt][nb][3]);
                    d[mt][nb][0] = d[mt][nb][1] = d[mt][nb][2] = d[mt][nb][3] = 0.0f;
                }
            }
        }

        const uint32_t st = sb + (c & 1) * STG;
        const uint32_t bslot = st + 16384 + gate * 8192;
        #pragma unroll
        for (int kk = 0; kk < 4; kk++) {
            uint32_t a[4][4];
            #pragma unroll
            for (int mt = 0; mt < 4; mt++) {
                int m = mh * 64 + mt * 16 + (l & 15);
                int kg = kk * 2 + (l >> 4);
                ldsm4(a[mt], st + m * 128 + ((kg ^ (m & 7)) << 4));
            }
            uint32_t b[2][4];
            #pragma unroll
            for (int nq = 0; nq < 2; nq++) {
                int k = kk * 16 + (l & 15);
                int ng = nhf * 4 + nq * 2 + (l >> 4);
                ldsm4t(b[nq], bslot + k * 128 + ((ng ^ (k & 7)) << 4));
            }
            #pragma unroll
            for (int mt = 0; mt < 4; mt++)
                #pragma unroll
                for (int nb = 0; nb < 4; nb++)
                    mma16816(d[mt][nb], a[mt], b[nb >> 1] + (nb & 1) * 2);
        }
        __syncthreads();
    }

    // ---- epilogue: planes r | z | i_n in sC [128][196]; h_n in spill ----
    float* sC = (float*)sm;
    #pragma unroll
    for (int mt = 0; mt < 4; mt++) {
        int r0 = mh * 64 + mt * 16 + (l >> 2);
        int cc = gate * 64 + nhf * 32 + (l & 3) * 2;
        #pragma unroll
        for (int nb = 0; nb < 4; nb++) {
            *(float2*)&sC[r0 * 196 + cc + nb * 8] =
                make_float2(d[mt][nb][0], d[mt][nb][1]);
            *(float2*)&sC[(r0 + 8) * 196 + cc + nb * 8] =
                make_float2(d[mt][nb][2], d[mt][nb][3]);
        }
    }
    __syncthreads();

    #pragma unroll
    for (int i = 0; i < 22; i++) {
        int idx = i * 384 + tid;
        if (idx >= 128 * 64) break;
        int m = idx >> 6, j = idx & 63;
        int jg = j0 + j;
        float rc = sC[m * 196 + j];
        float zc = sC[m * 196 + 64 + j];
        float ic = sC[m * 196 + 128 + j];
        float hc = spill[m * 64 + j];
        float br  = __ldg(&bih[jg]) + __ldg(&bhh[jg]);
        float bz  = __ldg(&bih[NH + jg]) + __ldg(&bhh[NH + jg]);
        float bin = __ldg(&bih[2 * NH + jg]);
        float bhn = __ldg(&bhh[2 * NH + jg]);
        float r = 1.0f / (1.0f + expf(-(rc + br)));
        float z = 1.0f / (1.0f + expf(-(zc + bz)));
        float n = tanhf(ic + bin + r * (hc + bhn));
        float hold = g_h32[cur][(size_t)(m0 + m) * NH + jg];
        float hnew = (1.0f - z) * n + z * hold;
        g_h32[nxt][(size_t)(m0 + m) * NH + jg] = hnew;
        g_ah[nxt][(size_t)(m0 + m) * KA + jg] = __float2half(hnew);
    }
}

// ---------------- decode fc1: split-K partials (fp32 SIMT) ----------------
__global__ void k_out(const float* __restrict__ fc1w, int p) {
    __shared__ float As[32][68];
    __shared__ float Bs[32][80];
    const float* hh = g_h32[p];
    const int m0 = blockIdx.x * 64;
    const int ks = blockIdx.y;
    const int tid = threadIdx.x;
    const int tx = tid & 15, ty = tid >> 4;
    float acc[4][5] = {};
    for (int kt = 0; kt < 4; kt++) {
        int k0 = ks * 128 + kt * 32;
        #pragma unroll
        for (int u = 0; u < 2; u++) {
            int idx = tid + u * 256;
            int m = idx >> 3;
            int kq = (idx & 7) * 4;
            float4 va = *(const float4*)(hh + (size_t)(m0 + m) * NH + k0 + kq);
            As[kq + 0][m] = va.x; As[kq + 1][m] = va.y;
            As[kq + 2][m] = va.z; As[kq + 3][m] = va.w;
        }
        for (int idx = tid; idx < 80 * 32; idx += 256) {
            int n = idx >> 5, k = idx & 31;
            Bs[k][n] = (n < NI) ? fc1w[(size_t)n * NH + k0 + k] : 0.0f;
        }
        __syncthreads();
        #pragma unroll
        for (int k = 0; k < 32; k++) {
            float4 a4 = *(const float4*)&As[k][ty * 4];
            float a[4] = {a4.x, a4.y, a4.z, a4.w};
            float bb[5];
            #pragma unroll
            for (int j = 0; j < 5; j++) bb[j] = Bs[k][tx * 5 + j];
            #pragma unroll
            for (int i = 0; i < 4; i++)
                #pragma unroll
                for (int j = 0; j < 5; j++)
                    acc[i][j] += a[i] * bb[j];
        }
        __syncthreads();
    }
    #pragma unroll
    for (int i = 0; i < 4; i++) {
        int m = m0 + ty * 4 + i;
        #pragma unroll
        for (int j = 0; j < 5; j++) {
            int n = tx * 5 + j;
            if (n < NI)
                g_part[(size_t)ks * NB * NI + (size_t)m * NI + n] = acc[i][j];
        }
    }
}

__global__ void k_outred(const float* __restrict__ fc1b, int t, int nbuf) {
    int idx = blockIdx.x * blockDim.x + threadIdx.x;
    if (idx >= NB * NI) return;
    int b = idx / NI, i = idx - b * NI;
    float s = g_x32[(size_t)b * KX + i] + fc1b[i];
    #pragma unroll
    for (int p = 0; p < 8; p++) s += g_part[(size_t)p * NB * NI + idx];
    g_outb[(size_t)t * NB * NI + idx] = s;
    g_x32[(size_t)b * KX + i] = s;
    g_ah[nbuf][(size_t)b * KA + NH + i] = __float2half(s);
}

__global__ void k_final(const float* __restrict__ fc2w, const float* __restrict__ fc2b,
                        float* __restrict__ y) {
    int b = blockIdx.x;
    float s = 0.0f;
    for (int f = threadIdx.x; f < NT * NI; f += 256) {
        int t = f / NI, i = f - t * NI;
        s += g_outb[(size_t)t * NB * NI + (size_t)b * NI + i] * fc2w[f];
    }
    __shared__ float red[256];
    red[threadIdx.x] = s;
    __syncthreads();
    for (int off = 128; off > 0; off >>= 1) {
        if (threadIdx.x < off) red[threadIdx.x] += red[threadIdx.x + off];
        __syncthreads();
    }
    if (threadIdx.x == 0)
        y[b] = 1.0f / (1.0f + expf(-(red[0] + fc2b[0])));
}

// ---------------- launch ----------------
extern "C" void kernel_launch(void* const* d_in, const int* in_sizes, int n_in,
                              void* d_out, int out_size) {
    const float* enc  = (const float*)d_in[0];
    const float* dec  = (const float*)d_in[1];
    const float* w_ih = (const float*)d_in[2];
    const float* w_hh = (const float*)d_in[3];
    const float* b_ih = (const float*)d_in[4];
    const float* b_hh = (const float*)d_in[5];
    const float* fc1w = (const float*)d_in[6];
    const float* fc1b = (const float*)d_in[7];
    const float* fc2w = (const float*)d_in[8];
    const float* fc2b = (const float*)d_in[9];
    float* y = (float*)d_out;

    cudaFuncSetAttribute(k_gru, cudaFuncAttributeMaxDynamicSharedMemorySize, SMEM_BYTES);

    k_prep<<<(int)(((size_t)4 * KA * NH + 255) / 256), 256>>>(w_ih, w_hh);
    k_init<<<(NB * KA + 255) / 256, 256>>>();

    int cur = 0;
    for (int s = 0; s < 2 * NT; ++s) {
        if (s <= NT) {
            int f = (s == NT) ? 0 : s;
            const float* src;
            int stride;
            if (f < NSRC) { src = enc + (size_t)f * NI; stride = NSRC * NI; }
            else          { src = dec + (size_t)(f - NSRC) * NI; stride = NDEC * NI; }
            k_setx<<<(NB * KX + 255) / 256, 256>>>(src, stride, cur);
        }
        k_gru<<<dim3(16, 8), 384, SMEM_BYTES>>>(cur, b_ih, b_hh);
        if (s >= NT) {
            k_out<<<dim3(16, 8), 256>>>(fc1w, cur ^ 1);
            k_outred<<<(NB * NI + 255) / 256, 256>>>(fc1b, s - NT, cur ^ 1);
        }
        cur ^= 1;
    }
    k_final<<<NB, 256>>>(fc2w, fc2b, y);
}

// round 7
// speedup vs baseline: 1.5168x; 1.0160x over previous
#include <cuda_runtime.h>
#include <cuda_fp16.h>
#include <cstdint>
#include <math.h>

// ---------------- problem constants ----------------
constexpr int NB   = 1024;
constexpr int NH   = 1024;
constexpr int NI   = 69;
constexpr int NSRC = 50;
constexpr int NDEC = 24;
constexpr int NT   = 74;
constexpr int KX   = 128;
constexpr int KA   = NH + KX;     // 1152
constexpr int NCHUNK = KA / 64;   // 18

constexpr int STG  = 40960;               // A 16KB + B 3x8KB
constexpr int SPILL_OFF = 100352;         // after epilogue sC (128x196 fp32)
constexpr int SMEM_BYTES = SPILL_OFF + 128 * 64 * 4;   // 133120

// ---------------- device scratch ----------------
__device__ __align__(16) float  g_h32[2][NB * NH];
__device__ __align__(16) __half g_ah[2][NB * KA];    // fp16 aug activations [b][k] = h|x
__device__ __align__(16) __half g_wB[4 * KA * NH];   // [g][k][j] fp16
__device__ __align__(16) float  g_x32[NB * KX];
__device__ __align__(16) float  g_outb[NT * NB * NI];
__device__ __align__(16) float  g_part[8 * NB * NI];

// ---------------- asm helpers (base PTX only) ----------------
__device__ __forceinline__ uint32_t smem_u32(const void* p) {
    uint32_t a;
    asm("{ .reg .u64 t; cvta.to.shared.u64 t, %1; cvt.u32.u64 %0, t; }" : "=r"(a) : "l"(p));
    return a;
}
__device__ __forceinline__ void cp16(uint32_t dst, const void* src) {
    asm volatile("cp.async.cg.shared.global [%0], [%1], 16;" :: "r"(dst), "l"(src));
}
__device__ __forceinline__ void cp_commit() {
    asm volatile("cp.async.commit_group;" ::: "memory");
}
__device__ __forceinline__ void ldsm4(uint32_t* r, uint32_t addr) {
    asm volatile("ldmatrix.sync.aligned.m8n8.x4.shared.b16 {%0,%1,%2,%3}, [%4];"
        : "=r"(r[0]), "=r"(r[1]), "=r"(r[2]), "=r"(r[3]) : "r"(addr));
}
__device__ __forceinline__ void ldsm4t(uint32_t* r, uint32_t addr) {
    asm volatile("ldmatrix.sync.aligned.m8n8.x4.trans.shared.b16 {%0,%1,%2,%3}, [%4];"
        : "=r"(r[0]), "=r"(r[1]), "=r"(r[2]), "=r"(r[3]) : "r"(addr));
}
__device__ __forceinline__ void mma16816(float* d, const uint32_t* a, const uint32_t* b) {
    asm volatile("mma.sync.aligned.m16n8k16.row.col.f32.f16.f16.f32 "
        "{%0,%1,%2,%3}, {%4,%5,%6,%7}, {%8,%9}, {%0,%1,%2,%3};"
        : "+f"(d[0]), "+f"(d[1]), "+f"(d[2]), "+f"(d[3])
        : "r"(a[0]), "r"(a[1]), "r"(a[2]), "r"(a[3]), "r"(b[0]), "r"(b[1]));
}

// ---------------- prep: per-gate K-major fp16 weights ----------------
// [g][k][j]: g0 r = [whh_r|wih_r], g1 z = [whh_z|wih_z],
//            g2 i_n = [0|wih_n],  g3 h_n = [whh_n|0]
__global__ void k_prep(const float* __restrict__ w_ih, const float* __restrict__ w_hh) {
    size_t idx = (size_t)blockIdx.x * blockDim.x + threadIdx.x;
    if (idx >= (size_t)4 * KA * NH) return;
    int j = (int)(idx % NH);
    int t = (int)(idx / NH);
    int k = t % KA;
    int g = t / KA;
    float v = 0.0f;
    if (g == 0) {
        if (k < NH) v = w_hh[(size_t)j * NH + k];
        else if (k - NH < NI) v = w_ih[(size_t)j * NI + (k - NH)];
    } else if (g == 1) {
        if (k < NH) v = w_hh[(size_t)(NH + j) * NH + k];
        else if (k - NH < NI) v = w_ih[(size_t)(NH + j) * NI + (k - NH)];
    } else if (g == 2) {
        if (k >= NH && k - NH < NI) v = w_ih[(size_t)(2 * NH + j) * NI + (k - NH)];
    } else {
        if (k < NH) v = w_hh[(size_t)(2 * NH + j) * NH + k];
    }
    g_wB[idx] = __float2half(v);
}

__global__ void k_init() {
    int idx = blockIdx.x * blockDim.x + threadIdx.x;
    if (idx < NB * KA) {
        g_ah[0][idx] = __float2half(0.0f);
        g_ah[1][idx] = __float2half(0.0f);
    }
    if (idx < NB * NH) g_h32[0][idx] = 0.0f;
}

__global__ void k_setx(const float* __restrict__ src, int stride, int buf) {
    int idx = blockIdx.x * blockDim.x + threadIdx.x;
    if (idx >= NB * KX) return;
    int b = idx >> 7, c = idx & (KX - 1);
    float v = (c < NI) ? src[(size_t)b * stride + c] : 0.0f;
    g_x32[idx] = v;
    g_ah[buf][(size_t)b * KA + NH + c] = __float2half(v);
}

// ---------------- fused GRU step ----------------
// grid (16 j-tiles, 8 m-tiles), 768 threads = 24 warps.
// warp: gate = wid/8 (0=r,1=z,2=n-slot); mq = (wid%8)>>1 (32-row slice);
//       nh = wid&1 (32-col half). warp tile 32m x 32n, 6 warps/SMSP.
// n-slot: h_n over chunks 0..15 (spilled), i_n over chunks 16..17.
__global__ void __launch_bounds__(768, 1)
k_gru(int cur, const float* __restrict__ bih, const float* __restrict__ bhh) {
    extern __shared__ char sm[];
    const uint32_t sb = smem_u32(sm);
    const int tid = threadIdx.x;
    const int wid = tid >> 5, l = tid & 31;
    const int gate = wid >> 3;
    const int mq = (wid >> 1) & 3, nh = wid & 1;
    const int m0 = blockIdx.y * 128;
    const int j0 = blockIdx.x * 64;
    const int nxt = cur ^ 1;

    const __half* A = g_ah[cur];

    float d[2][4][4] = {};   // [mt][nb][frag], 32 regs

    auto load_chunk = [&](int c) {
        const uint32_t st = sb + (c & 1) * STG;
        // 2560 granules: A 1024 (128m x 8kg), B 1536 (3 slots x 64k x 8cg)
        #pragma unroll
        for (int i = 0; i < 4; i++) {
            int v = tid + i * 768;
            if (v < 1024) {
                int m = v >> 3, kg = v & 7;
                cp16(st + m * 128 + ((kg ^ (m & 7)) << 4),
                     A + (size_t)(m0 + m) * KA + c * 64 + kg * 8);
            } else if (v < 2560) {
                int u = v - 1024;
                int tb = u >> 9;                 // 0..2 gate slot
                int r = (u >> 3) & 63, cg = u & 7;
                int g = (tb < 2) ? tb : ((c < 16) ? 3 : 2);
                cp16(st + 16384 + tb * 8192 + r * 128 + ((cg ^ (r & 7)) << 4),
                     g_wB + ((size_t)g * KA + c * 64 + r) * NH + j0 + cg * 8);
            }
        }
        cp_commit();
    };

    float* spill = (float*)(sm + SPILL_OFF);   // [128][64]

    load_chunk(0);
    for (int c = 0; c < NCHUNK; c++) {
        if (c + 1 < NCHUNK) {
            load_chunk(c + 1);
            asm volatile("cp.async.wait_group 1;" ::: "memory");
        } else {
            asm volatile("cp.async.wait_group 0;" ::: "memory");
        }
        __syncthreads();

        // n-slot boundary: stash h_n accum, restart for i_n
        if (c == 16 && gate == 2) {
            #pragma unroll
            for (int mt = 0; mt < 2; mt++) {
                int r0 = mq * 32 + mt * 16 + (l >> 2);
                int cc = nh * 32 + (l & 3) * 2;
                #pragma unroll
                for (int nb = 0; nb < 4; nb++) {
                    *(float2*)&spill[r0 * 64 + nb * 8 + cc] =
                        make_float2(d[mt][nb][0], d[mt][nb][1]);
                    *(float2*)&spill[(r0 + 8) * 64 + nb * 8 + cc] =
                        make_float2(d[mt][nb][2], d[mt][nb][3]);
                    d[mt][nb][0] = d[mt][nb][1] = d[mt][nb][2] = d[mt][nb][3] = 0.0f;
                }
            }
        }

        const uint32_t st = sb + (c & 1) * STG;
        const uint32_t bslot = st + 16384 + gate * 8192;
        #pragma unroll
        for (int kk = 0; kk < 4; kk++) {
            uint32_t a[2][4];
            #pragma unroll
            for (int mt = 0; mt < 2; mt++) {
                int m = mq * 32 + mt * 16 + (l & 15);
                int kg = kk * 2 + (l >> 4);
                ldsm4(a[mt], st + m * 128 + ((kg ^ (m & 7)) << 4));
            }
            uint32_t b[2][4];
            #pragma unroll
            for (int nq = 0; nq < 2; nq++) {
                int k = kk * 16 + (l & 15);
                int ng = nh * 4 + nq * 2 + (l >> 4);
                ldsm4t(b[nq], bslot + k * 128 + ((ng ^ (k & 7)) << 4));
            }
            #pragma unroll
            for (int mt = 0; mt < 2; mt++)
                #pragma unroll
                for (int nb = 0; nb < 4; nb++)
                    mma16816(d[mt][nb], a[mt], b[nb >> 1] + (nb & 1) * 2);
        }
        __syncthreads();
    }

    // ---- epilogue: planes r | z | i_n in sC [128][196]; h_n in spill ----
    float* sC = (float*)sm;
    #pragma unroll
    for (int mt = 0; mt < 2; mt++) {
        int r0 = mq * 32 + mt * 16 + (l >> 2);
        int cc = gate * 64 + nh * 32 + (l & 3) * 2;
        #pragma unroll
        for (int nb = 0; nb < 4; nb++) {
            *(float2*)&sC[r0 * 196 + cc + nb * 8] =
                make_float2(d[mt][nb][0], d[mt][nb][1]);
            *(float2*)&sC[(r0 + 8) * 196 + cc + nb * 8] =
                make_float2(d[mt][nb][2], d[mt][nb][3]);
        }
    }
    __syncthreads();

    #pragma unroll
    for (int i = 0; i < 11; i++) {
        int idx = i * 768 + tid;
        if (idx >= 128 * 64) break;
        int m = idx >> 6, j = idx & 63;
        int jg = j0 + j;
        float rc = sC[m * 196 + j];
        float zc = sC[m * 196 + 64 + j];
        float ic = sC[m * 196 + 128 + j];
        float hc = spill[m * 64 + j];
        float br  = __ldg(&bih[jg]) + __ldg(&bhh[jg]);
        float bz  = __ldg(&bih[NH + jg]) + __ldg(&bhh[NH + jg]);
        float bin = __ldg(&bih[2 * NH + jg]);
        float bhn = __ldg(&bhh[2 * NH + jg]);
        float r = 1.0f / (1.0f + expf(-(rc + br)));
        float z = 1.0f / (1.0f + expf(-(zc + bz)));
        float n = tanhf(ic + bin + r * (hc + bhn));
        float hold = g_h32[cur][(size_t)(m0 + m) * NH + jg];
        float hnew = (1.0f - z) * n + z * hold;
        g_h32[nxt][(size_t)(m0 + m) * NH + jg] = hnew;
        g_ah[nxt][(size_t)(m0 + m) * KA + jg] = __float2half(hnew);
    }
}

// ---------------- decode fc1: split-K partials (fp32 SIMT) ----------------
__global__ void k_out(const float* __restrict__ fc1w, int p) {
    __shared__ float As[32][68];
    __shared__ float Bs[32][80];
    const float* hh = g_h32[p];
    const int m0 = blockIdx.x * 64;
    const int ks = blockIdx.y;
    const int tid = threadIdx.x;
    const int tx = tid & 15, ty = tid >> 4;
    float acc[4][5] = {};
    for (int kt = 0; kt < 4; kt++) {
        int k0 = ks * 128 + kt * 32;
        #pragma unroll
        for (int u = 0; u < 2; u++) {
            int idx = tid + u * 256;
            int m = idx >> 3;
            int kq = (idx & 7) * 4;
            float4 va = *(const float4*)(hh + (size_t)(m0 + m) * NH + k0 + kq);
            As[kq + 0][m] = va.x; As[kq + 1][m] = va.y;
            As[kq + 2][m] = va.z; As[kq + 3][m] = va.w;
        }
        for (int idx = tid; idx < 80 * 32; idx += 256) {
            int n = idx >> 5, k = idx & 31;
            Bs[k][n] = (n < NI) ? fc1w[(size_t)n * NH + k0 + k] : 0.0f;
        }
        __syncthreads();
        #pragma unroll
        for (int k = 0; k < 32; k++) {
            float4 a4 = *(const float4*)&As[k][ty * 4];
            float a[4] = {a4.x, a4.y, a4.z, a4.w};
            float bb[5];
            #pragma unroll
            for (int j = 0; j < 5; j++) bb[j] = Bs[k][tx * 5 + j];
            #pragma unroll
            for (int i = 0; i < 4; i++)
                #pragma unroll
                for (int j = 0; j < 5; j++)
                    acc[i][j] += a[i] * bb[j];
        }
        __syncthreads();
    }
    #pragma unroll
    for (int i = 0; i < 4; i++) {
        int m = m0 + ty * 4 + i;
        #pragma unroll
        for (int j = 0; j < 5; j++) {
            int n = tx * 5 + j;
            if (n < NI)
                g_part[(size_t)ks * NB * NI + (size_t)m * NI + n] = acc[i][j];
        }
    }
}

__global__ void k_outred(const float* __restrict__ fc1b, int t, int nbuf) {
    int idx = blockIdx.x * blockDim.x + threadIdx.x;
    if (idx >= NB * NI) return;
    int b = idx / NI, i = idx - b * NI;
    float s = g_x32[(size_t)b * KX + i] + fc1b[i];
    #pragma unroll
    for (int p = 0; p < 8; p++) s += g_part[(size_t)p * NB * NI + idx];
    g_outb[(size_t)t * NB * NI + idx] = s;
    g_x32[(size_t)b * KX + i] = s;
    g_ah[nbuf][(size_t)b * KA + NH + i] = __float2half(s);
}

__global__ void k_final(const float* __restrict__ fc2w, const float* __restrict__ fc2b,
                        float* __restrict__ y) {
    int b = blockIdx.x;
    float s = 0.0f;
    for (int f = threadIdx.x; f < NT * NI; f += 256) {
        int t = f / NI, i = f - t * NI;
        s += g_outb[(size_t)t * NB * NI + (size_t)b * NI + i] * fc2w[f];
    }
    __shared__ float red[256];
    red[threadIdx.x] = s;
    __syncthreads();
    for (int off = 128; off > 0; off >>= 1) {
        if (threadIdx.x < off) red[threadIdx.x] += red[threadIdx.x + off];
        __syncthreads();
    }
    if (threadIdx.x == 0)
        y[b] = 1.0f / (1.0f + expf(-(red[0] + fc2b[0])));
}

// ---------------- launch ----------------
extern "C" void kernel_launch(void* const* d_in, const int* in_sizes, int n_in,
                              void* d_out, int out_size) {
    const float* enc  = (const float*)d_in[0];
    const float* dec  = (const float*)d_in[1];
    const float* w_ih = (const float*)d_in[2];
    const float* w_hh = (const float*)d_in[3];
    const float* b_ih = (const float*)d_in[4];
    const float* b_hh = (const float*)d_in[5];
    const float* fc1w = (const float*)d_in[6];
    const float* fc1b = (const float*)d_in[7];
    const float* fc2w = (const float*)d_in[8];
    const float* fc2b = (const float*)d_in[9];
    float* y = (float*)d_out;

    cudaFuncSetAttribute(k_gru, cudaFuncAttributeMaxDynamicSharedMemorySize, SMEM_BYTES);

    k_prep<<<(int)(((size_t)4 * KA * NH + 255) / 256), 256>>>(w_ih, w_hh);
    k_init<<<(NB * KA + 255) / 256, 256>>>();

    int cur = 0;
    for (int s = 0; s < 2 * NT; ++s) {
        if (s <= NT) {
            int f = (s == NT) ? 0 : s;
            const float* src;
            int stride;
            if (f < NSRC) { src = enc + (size_t)f * NI; stride = NSRC * NI; }
            else          { src = dec + (size_t)(f - NSRC) * NI; stride = NDEC * NI; }
            k_setx<<<(NB * KX + 255) / 256, 256>>>(src, stride, cur);
        }
        k_gru<<<dim3(16, 8), 768, SMEM_BYTES>>>(cur, b_ih, b_hh);
        if (s >= NT) {
            k_out<<<dim3(16, 8), 256>>>(fc1w, cur ^ 1);
            k_outred<<<(NB * NI + 255) / 256, 256>>>(fc1b, s - NT, cur ^ 1);
        }
        cur ^= 1;
    }
    k_final<<<NB, 256>>>(fc2w, fc2b, y);
}

// round 8
// speedup vs baseline: 1.5657x; 1.0322x over previous
#include <cuda_runtime.h>
#include <cuda_fp16.h>
#include <cstdint>
#include <math.h>

// ---------------- problem constants ----------------
constexpr int NB   = 1024;
constexpr int NH   = 1024;
constexpr int NI   = 69;
constexpr int NSRC = 50;
constexpr int NDEC = 24;
constexpr int NT   = 74;
constexpr int KX   = 128;
constexpr int KA   = NH + KX;     // 1152
constexpr int NCHUNK = KA / 64;   // 18

constexpr int STG  = 40960;               // A 16KB + B 3x8KB per stage
constexpr int SPILL_OFF = 3 * STG;        // 122880: h_n spill [128][64] fp32
constexpr int SMEM_BYTES = SPILL_OFF + 128 * 64 * 4;   // 155648

// ---------------- device scratch ----------------
__device__ __align__(16) float  g_h32[2][NB * NH];
__device__ __align__(16) __half g_ah[2][NB * KA];    // fp16 aug activations [b][k] = h|x
__device__ __align__(16) __half g_wB[4 * KA * NH];   // [g][k][j] fp16
__device__ __align__(16) float  g_x32[NB * KX];
__device__ __align__(16) float  g_outb[NT * NB * NI];
__device__ __align__(16) float  g_part[8 * NB * NI];

// ---------------- asm helpers (base PTX only) ----------------
__device__ __forceinline__ uint32_t smem_u32(const void* p) {
    uint32_t a;
    asm("{ .reg .u64 t; cvta.to.shared.u64 t, %1; cvt.u32.u64 %0, t; }" : "=r"(a) : "l"(p));
    return a;
}
__device__ __forceinline__ void cp16(uint32_t dst, const void* src) {
    asm volatile("cp.async.cg.shared.global [%0], [%1], 16;" :: "r"(dst), "l"(src));
}
__device__ __forceinline__ void cp_commit() {
    asm volatile("cp.async.commit_group;" ::: "memory");
}
__device__ __forceinline__ void ldsm4(uint32_t* r, uint32_t addr) {
    asm volatile("ldmatrix.sync.aligned.m8n8.x4.shared.b16 {%0,%1,%2,%3}, [%4];"
        : "=r"(r[0]), "=r"(r[1]), "=r"(r[2]), "=r"(r[3]) : "r"(addr));
}
__device__ __forceinline__ void ldsm4t(uint32_t* r, uint32_t addr) {
    asm volatile("ldmatrix.sync.aligned.m8n8.x4.trans.shared.b16 {%0,%1,%2,%3}, [%4];"
        : "=r"(r[0]), "=r"(r[1]), "=r"(r[2]), "=r"(r[3]) : "r"(addr));
}
__device__ __forceinline__ void mma16816(float* d, const uint32_t* a, const uint32_t* b) {
    asm volatile("mma.sync.aligned.m16n8k16.row.col.f32.f16.f16.f32 "
        "{%0,%1,%2,%3}, {%4,%5,%6,%7}, {%8,%9}, {%0,%1,%2,%3};"
        : "+f"(d[0]), "+f"(d[1]), "+f"(d[2]), "+f"(d[3])
        : "r"(a[0]), "r"(a[1]), "r"(a[2]), "r"(a[3]), "r"(b[0]), "r"(b[1]));
}

// ---------------- prep: per-gate K-major fp16 weights ----------------
// [g][k][j]: g0 r = [whh_r|wih_r], g1 z = [whh_z|wih_z],
//            g2 i_n = [0|wih_n],  g3 h_n = [whh_n|0]
__global__ void k_prep(const float* __restrict__ w_ih, const float* __restrict__ w_hh) {
    size_t idx = (size_t)blockIdx.x * blockDim.x + threadIdx.x;
    if (idx >= (size_t)4 * KA * NH) return;
    int j = (int)(idx % NH);
    int t = (int)(idx / NH);
    int k = t % KA;
    int g = t / KA;
    float v = 0.0f;
    if (g == 0) {
        if (k < NH) v = w_hh[(size_t)j * NH + k];
        else if (k - NH < NI) v = w_ih[(size_t)j * NI + (k - NH)];
    } else if (g == 1) {
        if (k < NH) v = w_hh[(size_t)(NH + j) * NH + k];
        else if (k - NH < NI) v = w_ih[(size_t)(NH + j) * NI + (k - NH)];
    } else if (g == 2) {
        if (k >= NH && k - NH < NI) v = w_ih[(size_t)(2 * NH + j) * NI + (k - NH)];
    } else {
        if (k < NH) v = w_hh[(size_t)(2 * NH + j) * NH + k];
    }
    g_wB[idx] = __float2half(v);
}

__global__ void k_init() {
    int idx = blockIdx.x * blockDim.x + threadIdx.x;
    if (idx < NB * KA) {
        g_ah[0][idx] = __float2half(0.0f);
        g_ah[1][idx] = __float2half(0.0f);
    }
    if (idx < NB * NH) g_h32[0][idx] = 0.0f;
}

__global__ void k_setx(const float* __restrict__ src, int stride, int buf) {
    int idx = blockIdx.x * blockDim.x + threadIdx.x;
    if (idx >= NB * KX) return;
    int b = idx >> 7, c = idx & (KX - 1);
    float v = (c < NI) ? src[(size_t)b * stride + c] : 0.0f;
    g_x32[idx] = v;
    g_ah[buf][(size_t)b * KA + NH + c] = __float2half(v);
}

// ---------------- fused GRU step ----------------
// grid (16 j-tiles, 8 m-tiles), 768 threads = 24 warps.
// warp: gate = wid/8 (0=r,1=z,2=n-slot); mq = (wid%8)>>1; nh = wid&1.
// warp tile 32m x 32n. 3-stage cp.async ring, ONE barrier per chunk.
// n-slot: h_n over chunks 0..15 (spilled), i_n over chunks 16..17.
__global__ void __launch_bounds__(768, 1)
k_gru(int cur, const float* __restrict__ bih, const float* __restrict__ bhh) {
    extern __shared__ char sm[];
    const uint32_t sb = smem_u32(sm);
    const int tid = threadIdx.x;
    const int wid = tid >> 5, l = tid & 31;
    const int gate = wid >> 3;
    const int mq = (wid >> 1) & 3, nh = wid & 1;
    const int m0 = blockIdx.y * 128;
    const int j0 = blockIdx.x * 64;
    const int nxt = cur ^ 1;

    const __half* A = g_ah[cur];

    float d[2][4][4] = {};   // [mt][nb][frag], 32 regs

    auto load_chunk = [&](int c) {
        const uint32_t st = sb + (c % 3) * STG;
        // 2560 granules: A 1024 (128m x 8kg), B 1536 (3 slots x 64k x 8cg)
        #pragma unroll
        for (int i = 0; i < 4; i++) {
            int v = tid + i * 768;
            if (v < 1024) {
                int m = v >> 3, kg = v & 7;
                cp16(st + m * 128 + ((kg ^ (m & 7)) << 4),
                     A + (size_t)(m0 + m) * KA + c * 64 + kg * 8);
            } else if (v < 2560) {
                int u = v - 1024;
                int tb = u >> 9;                 // 0..2 gate slot
                int r = (u >> 3) & 63, cg = u & 7;
                int g = (tb < 2) ? tb : ((c < 16) ? 3 : 2);
                cp16(st + 16384 + tb * 8192 + r * 128 + ((cg ^ (r & 7)) << 4),
                     g_wB + ((size_t)g * KA + c * 64 + r) * NH + j0 + cg * 8);
            }
        }
        cp_commit();
    };

    float* spill = (float*)(sm + SPILL_OFF);   // [128][64]

    load_chunk(0);
    load_chunk(1);
    for (int c = 0; c < NCHUNK; c++) {
        // groups pending: subset of {c, c+1}; need c complete
        if (c < NCHUNK - 1) {
            asm volatile("cp.async.wait_group 1;" ::: "memory");
        } else {
            asm volatile("cp.async.wait_group 0;" ::: "memory");
        }
        __syncthreads();   // the ONLY barrier per chunk

        // slot (c+2)%3 == (c-1)%3 is free: everyone finished compute(c-1)
        if (c + 2 < NCHUNK) load_chunk(c + 2);

        // n-slot boundary: stash h_n accum, restart for i_n
        if (c == 16 && gate == 2) {
            #pragma unroll
            for (int mt = 0; mt < 2; mt++) {
                int r0 = mq * 32 + mt * 16 + (l >> 2);
                int cc = nh * 32 + (l & 3) * 2;
                #pragma unroll
                for (int nb = 0; nb < 4; nb++) {
                    *(float2*)&spill[r0 * 64 + nb * 8 + cc] =
                        make_float2(d[mt][nb][0], d[mt][nb][1]);
                    *(float2*)&spill[(r0 + 8) * 64 + nb * 8 + cc] =
                        make_float2(d[mt][nb][2], d[mt][nb][3]);
                    d[mt][nb][0] = d[mt][nb][1] = d[mt][nb][2] = d[mt][nb][3] = 0.0f;
                }
            }
        }

        const uint32_t st = sb + (c % 3) * STG;
        const uint32_t bslot = st + 16384 + gate * 8192;
        #pragma unroll
        for (int kk = 0; kk < 4; kk++) {
            uint32_t a[2][4];
            #pragma unroll
            for (int mt = 0; mt < 2; mt++) {
                int m = mq * 32 + mt * 16 + (l & 15);
                int kg = kk * 2 + (l >> 4);
                ldsm4(a[mt], st + m * 128 + ((kg ^ (m & 7)) << 4));
            }
            uint32_t b[2][4];
            #pragma unroll
            for (int nq = 0; nq < 2; nq++) {
                int k = kk * 16 + (l & 15);
                int ng = nh * 4 + nq * 2 + (l >> 4);
                ldsm4t(b[nq], bslot + k * 128 + ((ng ^ (k & 7)) << 4));
            }
            #pragma unroll
            for (int mt = 0; mt < 2; mt++)
                #pragma unroll
                for (int nb = 0; nb < 4; nb++)
                    mma16816(d[mt][nb], a[mt], b[nb >> 1] + (nb & 1) * 2);
        }
        // no trailing barrier: stage ring + next iteration's barrier protect buffers
    }
    __syncthreads();   // epilogue sC overlays the stage region

    // ---- epilogue: planes r | z | i_n in sC [128][196]; h_n in spill ----
    float* sC = (float*)sm;
    #pragma unroll
    for (int mt = 0; mt < 2; mt++) {
        int r0 = mq * 32 + mt * 16 + (l >> 2);
        int cc = gate * 64 + nh * 32 + (l & 3) * 2;
        #pragma unroll
        for (int nb = 0; nb < 4; nb++) {
            *(float2*)&sC[r0 * 196 + cc + nb * 8] =
                make_float2(d[mt][nb][0], d[mt][nb][1]);
            *(float2*)&sC[(r0 + 8) * 196 + cc + nb * 8] =
                make_float2(d[mt][nb][2], d[mt][nb][3]);
        }
    }
    __syncthreads();

    #pragma unroll
    for (int i = 0; i < 11; i++) {
        int idx = i * 768 + tid;
        if (idx >= 128 * 64) break;
        int m = idx >> 6, j = idx & 63;
        int jg = j0 + j;
        float rc = sC[m * 196 + j];
        float zc = sC[m * 196 + 64 + j];
        float ic = sC[m * 196 + 128 + j];
        float hc = spill[m * 64 + j];
        float br  = __ldg(&bih[jg]) + __ldg(&bhh[jg]);
        float bz  = __ldg(&bih[NH + jg]) + __ldg(&bhh[NH + jg]);
        float bin = __ldg(&bih[2 * NH + jg]);
        float bhn = __ldg(&bhh[2 * NH + jg]);
        float r = 1.0f / (1.0f + expf(-(rc + br)));
        float z = 1.0f / (1.0f + expf(-(zc + bz)));
        float n = tanhf(ic + bin + r * (hc + bhn));
        float hold = g_h32[cur][(size_t)(m0 + m) * NH + jg];
        float hnew = (1.0f - z) * n + z * hold;
        g_h32[nxt][(size_t)(m0 + m) * NH + jg] = hnew;
        g_ah[nxt][(size_t)(m0 + m) * KA + jg] = __float2half(hnew);
    }
}

// ---------------- decode fc1: split-K partials (fp32 SIMT) ----------------
__global__ void k_out(const float* __restrict__ fc1w, int p) {
    __shared__ float As[32][68];
    __shared__ float Bs[32][80];
    const float* hh = g_h32[p];
    const int m0 = blockIdx.x * 64;
    const int ks = blockIdx.y;
    const int tid = threadIdx.x;
    const int tx = tid & 15, ty = tid >> 4;
    float acc[4][5] = {};
    for (int kt = 0; kt < 4; kt++) {
        int k0 = ks * 128 + kt * 32;
        #pragma unroll
        for (int u = 0; u < 2; u++) {
            int idx = tid + u * 256;
            int m = idx >> 3;
            int kq = (idx & 7) * 4;
            float4 va = *(const float4*)(hh + (size_t)(m0 + m) * NH + k0 + kq);
            As[kq + 0][m] = va.x; As[kq + 1][m] = va.y;
            As[kq + 2][m] = va.z; As[kq + 3][m] = va.w;
        }
        for (int idx = tid; idx < 80 * 32; idx += 256) {
            int n = idx >> 5, k = idx & 31;
            Bs[k][n] = (n < NI) ? fc1w[(size_t)n * NH + k0 + k] : 0.0f;
        }
        __syncthreads();
        #pragma unroll
        for (int k = 0; k < 32; k++) {
            float4 a4 = *(const float4*)&As[k][ty * 4];
            float a[4] = {a4.x, a4.y, a4.z, a4.w};
            float bb[5];
            #pragma unroll
            for (int j = 0; j < 5; j++) bb[j] = Bs[k][tx * 5 + j];
            #pragma unroll
            for (int i = 0; i < 4; i++)
                #pragma unroll
                for (int j = 0; j < 5; j++)
                    acc[i][j] += a[i] * bb[j];
        }
        __syncthreads();
    }
    #pragma unroll
    for (int i = 0; i < 4; i++) {
        int m = m0 + ty * 4 + i;
        #pragma unroll
        for (int j = 0; j < 5; j++) {
            int n = tx * 5 + j;
            if (n < NI)
                g_part[(size_t)ks * NB * NI + (size_t)m * NI + n] = acc[i][j];
        }
    }
}

__global__ void k_outred(const float* __restrict__ fc1b, int t, int nbuf) {
    int idx = blockIdx.x * blockDim.x + threadIdx.x;
    if (idx >= NB * NI) return;
    int b = idx / NI, i = idx - b * NI;
    float s = g_x32[(size_t)b * KX + i] + fc1b[i];
    #pragma unroll
    for (int p = 0; p < 8; p++) s += g_part[(size_t)p * NB * NI + idx];
    g_outb[(size_t)t * NB * NI + idx] = s;
    g_x32[(size_t)b * KX + i] = s;
    g_ah[nbuf][(size_t)b * KA + NH + i] = __float2half(s);
}

__global__ void k_final(const float* __restrict__ fc2w, const float* __restrict__ fc2b,
                        float* __restrict__ y) {
    int b = blockIdx.x;
    float s = 0.0f;
    for (int f = threadIdx.x; f < NT * NI; f += 256) {
        int t = f / NI, i = f - t * NI;
        s += g_outb[(size_t)t * NB * NI + (size_t)b * NI + i] * fc2w[f];
    }
    __shared__ float red[256];
    red[threadIdx.x] = s;
    __syncthreads();
    for (int off = 128; off > 0; off >>= 1) {
        if (threadIdx.x < off) red[threadIdx.x] += red[threadIdx.x + off];
        __syncthreads();
    }
    if (threadIdx.x == 0)
        y[b] = 1.0f / (1.0f + expf(-(red[0] + fc2b[0])));
}

// ---------------- launch ----------------
extern "C" void kernel_launch(void* const* d_in, const int* in_sizes, int n_in,
                              void* d_out, int out_size) {
    const float* enc  = (const float*)d_in[0];
    const float* dec  = (const float*)d_in[1];
    const float* w_ih = (const float*)d_in[2];
    const float* w_hh = (const float*)d_in[3];
    const float* b_ih = (const float*)d_in[4];
    const float* b_hh = (const float*)d_in[5];
    const float* fc1w = (const float*)d_in[6];
    const float* fc1b = (const float*)d_in[7];
    const float* fc2w = (const float*)d_in[8];
    const float* fc2b = (const float*)d_in[9];
    float* y = (float*)d_out;

    cudaFuncSetAttribute(k_gru, cudaFuncAttributeMaxDynamicSharedMemorySize, SMEM_BYTES);

    k_prep<<<(int)(((size_t)4 * KA * NH + 255) / 256), 256>>>(w_ih, w_hh);
    k_init<<<(NB * KA + 255) / 256, 256>>>();

    int cur = 0;
    for (int s = 0; s < 2 * NT; ++s) {
        if (s <= NT) {
            int f = (s == NT) ? 0 : s;
            const float* src;
            int stride;
            if (f < NSRC) { src = enc + (size_t)f * NI; stride = NSRC * NI; }
            else          { src = dec + (size_t)(f - NSRC) * NI; stride = NDEC * NI; }
            k_setx<<<(NB * KX + 255) / 256, 256>>>(src, stride, cur);
        }
        k_gru<<<dim3(16, 8), 768, SMEM_BYTES>>>(cur, b_ih, b_hh);
        if (s >= NT) {
            k_out<<<dim3(16, 8), 256>>>(fc1w, cur ^ 1);
            k_outred<<<(NB * NI + 255) / 256, 256>>>(fc1b, s - NT, cur ^ 1);
        }
        cur ^= 1;
    }
    k_final<<<NB, 256>>>(fc2w, fc2b, y);
}

// round 9
// speedup vs baseline: 1.7829x; 1.1387x over previous
#include <cuda_runtime.h>
#include <cuda_fp16.h>
#include <cstdint>
#include <math.h>

// ---------------- problem constants ----------------
constexpr int NB   = 1024;
constexpr int NH   = 1024;
constexpr int NI   = 69;
constexpr int NSRC = 50;
constexpr int NDEC = 24;
constexpr int NT   = 74;
constexpr int KX   = 128;
constexpr int KA   = NH + KX;     // 1152
constexpr int NCHUNK = KA / 64;   // 18

constexpr int STG  = 32768;               // A 8KB + B 3x8KB per stage
constexpr int SPILL_OFF = 3 * STG;        // 98304: h_n spill [64][68] fp32
constexpr int SMEM_BYTES = SPILL_OFF + 64 * 68 * 4;   // 115712 (2 CTAs/SM)
constexpr int W1_OFF = 2 * STG;           // fc1: abuf @ stage2, w1 @ stage2+8KB

// ---------------- device scratch ----------------
__device__ __align__(16) float  g_h32[2][NB * NH];
__device__ __align__(16) __half g_ah[2][NB * KA];    // fp16 aug activations [b][k] = h|x
__device__ __align__(16) __half g_wB[4 * KA * NH];   // [g][k][j] fp16
__device__ __align__(16) __half g_w1h[2 * NH * 64];  // fc1 w [slot][j][i-in-slot] fp16
__device__ __align__(16) float  g_x32[NB * KX];
__device__ __align__(16) float  g_outb[NT * NB * NI];
__device__ __align__(16) float  g_part[16 * NB * NI];

// ---------------- asm helpers (base PTX only) ----------------
__device__ __forceinline__ uint32_t smem_u32(const void* p) {
    uint32_t a;
    asm("{ .reg .u64 t; cvta.to.shared.u64 t, %1; cvt.u32.u64 %0, t; }" : "=r"(a) : "l"(p));
    return a;
}
__device__ __forceinline__ void cp16(uint32_t dst, const void* src) {
    asm volatile("cp.async.cg.shared.global [%0], [%1], 16;" :: "r"(dst), "l"(src));
}
__device__ __forceinline__ void cp_commit() {
    asm volatile("cp.async.commit_group;" ::: "memory");
}
__device__ __forceinline__ void ldsm4(uint32_t* r, uint32_t addr) {
    asm volatile("ldmatrix.sync.aligned.m8n8.x4.shared.b16 {%0,%1,%2,%3}, [%4];"
        : "=r"(r[0]), "=r"(r[1]), "=r"(r[2]), "=r"(r[3]) : "r"(addr));
}
__device__ __forceinline__ void ldsm4t(uint32_t* r, uint32_t addr) {
    asm volatile("ldmatrix.sync.aligned.m8n8.x4.trans.shared.b16 {%0,%1,%2,%3}, [%4];"
        : "=r"(r[0]), "=r"(r[1]), "=r"(r[2]), "=r"(r[3]) : "r"(addr));
}
__device__ __forceinline__ void mma16816(float* d, const uint32_t* a, const uint32_t* b) {
    asm volatile("mma.sync.aligned.m16n8k16.row.col.f32.f16.f16.f32 "
        "{%0,%1,%2,%3}, {%4,%5,%6,%7}, {%8,%9}, {%0,%1,%2,%3};"
        : "+f"(d[0]), "+f"(d[1]), "+f"(d[2]), "+f"(d[3])
        : "r"(a[0]), "r"(a[1]), "r"(a[2]), "r"(a[3]), "r"(b[0]), "r"(b[1]));
}
__device__ __forceinline__ uint32_t sw(uint32_t bo) { return bo ^ ((bo >> 3) & 0x70); }

// ---------------- prep: per-gate K-major fp16 weights ----------------
__global__ void k_prep(const float* __restrict__ w_ih, const float* __restrict__ w_hh) {
    size_t idx = (size_t)blockIdx.x * blockDim.x + threadIdx.x;
    if (idx >= (size_t)4 * KA * NH) return;
    int j = (int)(idx % NH);
    int t = (int)(idx / NH);
    int k = t % KA;
    int g = t / KA;
    float v = 0.0f;
    if (g == 0) {
        if (k < NH) v = w_hh[(size_t)j * NH + k];
        else if (k - NH < NI) v = w_ih[(size_t)j * NI + (k - NH)];
    } else if (g == 1) {
        if (k < NH) v = w_hh[(size_t)(NH + j) * NH + k];
        else if (k - NH < NI) v = w_ih[(size_t)(NH + j) * NI + (k - NH)];
    } else if (g == 2) {
        if (k >= NH && k - NH < NI) v = w_ih[(size_t)(2 * NH + j) * NI + (k - NH)];
    } else {
        if (k < NH) v = w_hh[(size_t)(2 * NH + j) * NH + k];
    }
    g_wB[idx] = __float2half(v);
}

// fc1 weights, k-major per 64-wide i-slot: g_w1h[s][j][n], i = s*64+n
__global__ void k_prepw(const float* __restrict__ fc1w) {
    int idx = blockIdx.x * blockDim.x + threadIdx.x;
    if (idx >= 2 * NH * 64) return;
    int n = idx & 63;
    int j = (idx >> 6) & (NH - 1);
    int s = idx >> 16;
    int i = s * 64 + n;
    float v = (i < NI) ? fc1w[(size_t)i * NH + j] : 0.0f;
    g_w1h[idx] = __float2half(v);
}

__global__ void k_init() {
    int idx = blockIdx.x * blockDim.x + threadIdx.x;
    if (idx < NB * KA) {
        g_ah[0][idx] = __float2half(0.0f);
        g_ah[1][idx] = __float2half(0.0f);
    }
    if (idx < NB * NH) g_h32[0][idx] = 0.0f;
}

__global__ void k_setx(const float* __restrict__ src, int stride, int buf) {
    int idx = blockIdx.x * blockDim.x + threadIdx.x;
    if (idx >= NB * KX) return;
    int b = idx >> 7, c = idx & (KX - 1);
    float v = (c < NI) ? src[(size_t)b * stride + c] : 0.0f;
    g_x32[idx] = v;
    g_ah[buf][(size_t)b * KA + NH + c] = __float2half(v);
}

// ---------------- fused GRU step ----------------
// grid (16 j-tiles, 16 m-tiles), 384 threads = 12 warps, 2 CTAs/SM.
// warp: gate = wid>>2 (0=r,1=z,2=n-slot); mq = (wid>>1)&1; nh = wid&1.
// CTA tile 64m x 64j, warp tile 32m x 32n. 3-stage ring, one barrier/chunk.
// do_fc1: epilogue runs 64x128x64 fp16 MMA (h_new @ w1^T) -> g_part[jt].
__global__ void __launch_bounds__(384, 2)
k_gru(int cur, const float* __restrict__ bih, const float* __restrict__ bhh,
      int do_fc1) {
    extern __shared__ char sm[];
    const uint32_t sb = smem_u32(sm);
    const int tid = threadIdx.x;
    const int wid = tid >> 5, l = tid & 31;
    const int gate = wid >> 2;
    const int mq = (wid >> 1) & 1, nh = wid & 1;
    const int m0 = blockIdx.y * 64;
    const int j0 = blockIdx.x * 64;
    const int jt = blockIdx.x;
    const int nxt = cur ^ 1;

    const __half* A = g_ah[cur];

    float d[2][4][4] = {};   // [mt][nb][frag]

    auto load_chunk = [&](int c) {
        const uint32_t st = sb + (c % 3) * STG;
        // 2048 granules: A 512 (64m x 8kg), B 1536 (3 slots x 64k x 8cg)
        #pragma unroll
        for (int i = 0; i < 6; i++) {
            int v = tid + i * 384;
            if (v < 512) {
                int m = v >> 3, kg = v & 7;
                cp16(st + m * 128 + ((kg ^ (m & 7)) << 4),
                     A + (size_t)(m0 + m) * KA + c * 64 + kg * 8);
            } else if (v < 2048) {
                int u = v - 512;
                int tb = u >> 9;                 // 0..2 gate slot
                int r = (u >> 3) & 63, cg = u & 7;
                int g = (tb < 2) ? tb : ((c < 16) ? 3 : 2);
                cp16(st + 8192 + tb * 8192 + r * 128 + ((cg ^ (r & 7)) << 4),
                     g_wB + ((size_t)g * KA + c * 64 + r) * NH + j0 + cg * 8);
            }
        }
        cp_commit();
    };

    float* spill = (float*)(sm + SPILL_OFF);   // [64][68]

    load_chunk(0);
    load_chunk(1);
    for (int c = 0; c < NCHUNK; c++) {
        if (c < NCHUNK - 1) {
            asm volatile("cp.async.wait_group 1;" ::: "memory");
        } else {
            asm volatile("cp.async.wait_group 0;" ::: "memory");
        }
        __syncthreads();   // the ONLY barrier per chunk

        if (c + 2 < NCHUNK) load_chunk(c + 2);

        // n-slot boundary: stash h_n accum, restart for i_n
        if (c == 16 && gate == 2) {
            #pragma unroll
            for (int mt = 0; mt < 2; mt++) {
                int r0 = mq * 32 + mt * 16 + (l >> 2);
                int cc = nh * 32 + (l & 3) * 2;
                #pragma unroll
                for (int nb = 0; nb < 4; nb++) {
                    *(float2*)&spill[r0 * 68 + nb * 8 + cc] =
                        make_float2(d[mt][nb][0], d[mt][nb][1]);
                    *(float2*)&spill[(r0 + 8) * 68 + nb * 8 + cc] =
                        make_float2(d[mt][nb][2], d[mt][nb][3]);
                    d[mt][nb][0] = d[mt][nb][1] = d[mt][nb][2] = d[mt][nb][3] = 0.0f;
                }
            }
        }

        const uint32_t st = sb + (c % 3) * STG;
        const uint32_t bslot = st + 8192 + gate * 8192;
        #pragma unroll
        for (int kk = 0; kk < 4; kk++) {
            uint32_t a[2][4];
            #pragma unroll
            for (int mt = 0; mt < 2; mt++) {
                int m = mq * 32 + mt * 16 + (l & 15);
                int kg = kk * 2 + (l >> 4);
                ldsm4(a[mt], st + m * 128 + ((kg ^ (m & 7)) << 4));
            }
            uint32_t b[2][4];
            #pragma unroll
            for (int nq = 0; nq < 2; nq++) {
                int k = kk * 16 + (l & 15);
                int ng = nh * 4 + nq * 2 + (l >> 4);
                ldsm4t(b[nq], bslot + k * 128 + ((ng ^ (k & 7)) << 4));
            }
            #pragma unroll
            for (int mt = 0; mt < 2; mt++)
                #pragma unroll
                for (int nb = 0; nb < 4; nb++)
                    mma16816(d[mt][nb], a[mt], b[nb >> 1] + (nb & 1) * 2);
        }
    }
    __syncthreads();   // all compute done; stages reusable

    // fc1 weight slice load into stage2+8KB (overlaps epilogue below)
    if (do_fc1) {
        #pragma unroll
        for (int i = 0; i < 3; i++) {
            int v = tid + i * 384;
            if (v < 1024) {
                int s = v >> 9, r = (v >> 3) & 63, cg = v & 7;
                cp16(sb + W1_OFF + 8192 + s * 8192 + r * 128 + ((cg ^ (r & 7)) << 4),
                     g_w1h + ((size_t)s * NH + j0 + r) * 64 + cg * 8);
            }
        }
        cp_commit();
    }

    // ---- epilogue: planes r | z | i_n in sC [64][196]; h_n in spill ----
    float* sC = (float*)sm;
    #pragma unroll
    for (int mt = 0; mt < 2; mt++) {
        int r0 = mq * 32 + mt * 16 + (l >> 2);
        int cc = gate * 64 + nh * 32 + (l & 3) * 2;
        #pragma unroll
        for (int nb = 0; nb < 4; nb++) {
            *(float2*)&sC[r0 * 196 + cc + nb * 8] =
                make_float2(d[mt][nb][0], d[mt][nb][1]);
            *(float2*)&sC[(r0 + 8) * 196 + cc + nb * 8] =
                make_float2(d[mt][nb][2], d[mt][nb][3]);
        }
    }
    __syncthreads();

    #pragma unroll
    for (int i = 0; i < 11; i++) {
        int idx = i * 384 + tid;
        if (idx >= 64 * 64) break;
        int m = idx >> 6, j = idx & 63;
        int jg = j0 + j;
        float rc = sC[m * 196 + j];
        float zc = sC[m * 196 + 64 + j];
        float ic = sC[m * 196 + 128 + j];
        float hc = spill[m * 68 + j];
        float br  = __ldg(&bih[jg]) + __ldg(&bhh[jg]);
        float bz  = __ldg(&bih[NH + jg]) + __ldg(&bhh[NH + jg]);
        float bin = __ldg(&bih[2 * NH + jg]);
        float bhn = __ldg(&bhh[2 * NH + jg]);
        float r = 1.0f / (1.0f + expf(-(rc + br)));
        float z = 1.0f / (1.0f + expf(-(zc + bz)));
        float n = tanhf(ic + bin + r * (hc + bhn));
        float hold = g_h32[cur][(size_t)(m0 + m) * NH + jg];
        float hnew = (1.0f - z) * n + z * hold;
        g_h32[nxt][(size_t)(m0 + m) * NH + jg] = hnew;
        __half h16 = __float2half(hnew);
        g_ah[nxt][(size_t)(m0 + m) * KA + jg] = h16;
        if (do_fc1)   // stage2 region: h tile k-major for the fc1 MMA
            *(__half*)(sm + W1_OFF + sw((uint32_t)(m * 128 + j * 2))) = h16;
    }

    if (do_fc1) {
        asm volatile("cp.async.wait_group 0;" ::: "memory");
        __syncthreads();
        // 64m x 128n(i pad) x 64k(j): 8 warps, warp tile 32x32
        if (wid < 8) {
            const int wm = wid >> 2, wn = wid & 3;
            float d2[2][4][4] = {};
            const uint32_t ab = sb + W1_OFF;
            const uint32_t bb = sb + W1_OFF + 8192 + (wn >> 1) * 8192;
            #pragma unroll
            for (int kk = 0; kk < 4; kk++) {
                uint32_t a[2][4];
                #pragma unroll
                for (int mt = 0; mt < 2; mt++) {
                    int m = wm * 32 + mt * 16 + (l & 15);
                    int kg = kk * 2 + (l >> 4);
                    ldsm4(a[mt], ab + m * 128 + ((kg ^ (m & 7)) << 4));
                }
                uint32_t b[2][4];
                #pragma unroll
                for (int nq = 0; nq < 2; nq++) {
                    int k = kk * 16 + (l & 15);
                    int ng = (wn & 1) * 4 + nq * 2 + (l >> 4);
                    ldsm4t(b[nq], bb + k * 128 + ((ng ^ (k & 7)) << 4));
                }
                #pragma unroll
                for (int mt = 0; mt < 2; mt++)
                    #pragma unroll
                    for (int nb = 0; nb < 4; nb++)
                        mma16816(d2[mt][nb], a[mt], b[nb >> 1] + (nb & 1) * 2);
            }
            // store partials (only i < 69)
            #pragma unroll
            for (int mt = 0; mt < 2; mt++) {
                int mg = m0 + wm * 32 + mt * 16 + (l >> 2);
                #pragma unroll
                for (int nb = 0; nb < 4; nb++) {
                    int n = wn * 32 + nb * 8 + (l & 3) * 2;
                    size_t base = (size_t)jt * NB * NI;
                    if (n < NI)     g_part[base + (size_t)mg * NI + n]       = d2[mt][nb][0];
                    if (n + 1 < NI) g_part[base + (size_t)mg * NI + n + 1]   = d2[mt][nb][1];
                    if (n < NI)     g_part[base + (size_t)(mg + 8) * NI + n] = d2[mt][nb][2];
                    if (n + 1 < NI) g_part[base + (size_t)(mg + 8) * NI + n + 1] = d2[mt][nb][3];
                }
            }
        }
    }
}

// out[t] = x + fc1_b + sum of 16 j-tile partials ; becomes next step's x
__global__ void k_outred(const float* __restrict__ fc1b, int t, int nbuf) {
    int idx = blockIdx.x * blockDim.x + threadIdx.x;
    if (idx >= NB * NI) return;
    int b = idx / NI, i = idx - b * NI;
    float s = g_x32[(size_t)b * KX + i] + fc1b[i];
    #pragma unroll
    for (int p = 0; p < 16; p++) s += g_part[(size_t)p * NB * NI + idx];
    g_outb[(size_t)t * NB * NI + idx] = s;
    g_x32[(size_t)b * KX + i] = s;
    g_ah[nbuf][(size_t)b * KA + NH + i] = __float2half(s);
}

__global__ void k_final(const float* __restrict__ fc2w, const float* __restrict__ fc2b,
                        float* __restrict__ y) {
    int b = blockIdx.x;
    float s = 0.0f;
    for (int f = threadIdx.x; f < NT * NI; f += 256) {
        int t = f / NI, i = f - t * NI;
        s += g_outb[(size_t)t * NB * NI + (size_t)b * NI + i] * fc2w[f];
    }
    __shared__ float red[256];
    red[threadIdx.x] = s;
    __syncthreads();
    for (int off = 128; off > 0; off >>= 1) {
        if (threadIdx.x < off) red[threadIdx.x] += red[threadIdx.x + off];
        __syncthreads();
    }
    if (threadIdx.x == 0)
        y[b] = 1.0f / (1.0f + expf(-(red[0] + fc2b[0])));
}

// ---------------- launch ----------------
extern "C" void kernel_launch(void* const* d_in, const int* in_sizes, int n_in,
                              void* d_out, int out_size) {
    const float* enc  = (const float*)d_in[0];
    const float* dec  = (const float*)d_in[1];
    const float* w_ih = (const float*)d_in[2];
    const float* w_hh = (const float*)d_in[3];
    const float* b_ih = (const float*)d_in[4];
    const float* b_hh = (const float*)d_in[5];
    const float* fc1w = (const float*)d_in[6];
    const float* fc1b = (const float*)d_in[7];
    const float* fc2w = (const float*)d_in[8];
    const float* fc2b = (const float*)d_in[9];
    float* y = (float*)d_out;

    cudaFuncSetAttribute(k_gru, cudaFuncAttributeMaxDynamicSharedMemorySize, SMEM_BYTES);

    k_prep<<<(int)(((size_t)4 * KA * NH + 255) / 256), 256>>>(w_ih, w_hh);
    k_prepw<<<(2 * NH * 64 + 255) / 256, 256>>>(fc1w);
    k_init<<<(NB * KA + 255) / 256, 256>>>();

    int cur = 0;
    for (int s = 0; s < 2 * NT; ++s) {
        if (s <= NT) {
            int f = (s == NT) ? 0 : s;
            const float* src;
            int stride;
            if (f < NSRC) { src = enc + (size_t)f * NI; stride = NSRC * NI; }
            else          { src = dec + (size_t)(f - NSRC) * NI; stride = NDEC * NI; }
            k_setx<<<(NB * KX + 255) / 256, 256>>>(src, stride, cur);
        }
        int do_fc1 = (s >= NT) ? 1 : 0;
        k_gru<<<dim3(16, 16), 384, SMEM_BYTES>>>(cur, b_ih, b_hh, do_fc1);
        if (s >= NT)
            k_outred<<<(NB * NI + 255) / 256, 256>>>(fc1b, s - NT, cur ^ 1);
        cur ^= 1;
    }
    k_final<<<NB, 256>>>(fc2w, fc2b, y);
}